// round 15
// baseline (speedup 1.0000x reference)
#include <cuda_runtime.h>
#include <cuda_fp16.h>
#include <cstdint>

// Problem dims
#define M_TOT 32768
#define K_TOT 1024
#define N_TOT 1024
#define RNK   16
#define NPLANE 5
#define XA_COLS 80

// ---------------- scratch ----------------
__device__ __half g_xh[(size_t)M_TOT * K_TOT];        // x in fp16 (written by xa blocks)
__device__ __half g_wh[(size_t)N_TOT * K_TOT];        // W in fp16 (written by cvt blocks)
__device__ __half g_bh[(size_t)NPLANE * N_TOT * RNK]; // [B_sh; B_tasks] fp16 (cvt blocks)
__device__ __half g_xah[(size_t)M_TOT * XA_COLS];     // XA result fp16

__device__ __forceinline__ uint32_t smem_u32(const void* p) {
    return (uint32_t)__cvta_generic_to_shared(p);
}
#define CP16(d, s) asm volatile("cp.async.cg.shared.global [%0], [%1], 16;" ::"r"(d), "l"(s))
#define CPC() asm volatile("cp.async.commit_group;")
#define CPW(n) asm volatile("cp.async.wait_group %0;" ::"n"(n))

// fp16 mma, fp32 accum
__device__ __forceinline__ void mma16(float c[4], unsigned a0, unsigned a1, unsigned a2,
                                      unsigned a3, unsigned b0, unsigned b1) {
    asm volatile(
        "mma.sync.aligned.m16n8k16.row.col.f32.f16.f16.f32 "
        "{%0,%1,%2,%3},{%4,%5,%6,%7},{%8,%9},{%0,%1,%2,%3};"
        : "+f"(c[0]), "+f"(c[1]), "+f"(c[2]), "+f"(c[3])
        : "r"(a0), "r"(a1), "r"(a2), "r"(a3), "r"(b0), "r"(b1));
}

__device__ __forceinline__ void cvt8(const float* s, __half* d) {
    float4 v0 = *(const float4*)s;
    float4 v1 = *(const float4*)(s + 4);
    __half2 h0 = __floats2half2_rn(v0.x, v0.y), h1 = __floats2half2_rn(v0.z, v0.w);
    __half2 h2 = __floats2half2_rn(v1.x, v1.y), h3 = __floats2half2_rn(v1.z, v1.w);
    uint4 o;
    o.x = *(uint32_t*)&h0; o.y = *(uint32_t*)&h1;
    o.z = *(uint32_t*)&h2; o.w = *(uint32_t*)&h3;
    *(uint4*)d = o;
}

// ---------------------------------------------------------------------------
// Kernel 1 (fused): blocks [0,512):   XA = x @ [A_sh; A_tasks]^T  AND x->fp16
//                   blocks [512,1024): W -> g_wh
//                   blocks [1024,1064): [B_sh;B_tasks] -> g_bh
// xa blocks: CTA 64 rows, 8 warps as 4x2 (warp 16x40), occupancy 2.
// Both x and A read in f32 and converted in-register; 3-stage pipeline.
// ---------------------------------------------------------------------------
#define X_BM 64
#define X_ASTG 8192                  // 64 rows * 128 B (f32)
#define X_BSTG 10240                 // 80 rows * 128 B (f32)
#define X_STG (X_ASTG + X_BSTG)      // 18432
#define X_SMEM (3 * X_STG)           // 55296

__global__ void __launch_bounds__(256, 2) xa_kernel(
    const float* __restrict__ x, const float* __restrict__ W,
    const float* __restrict__ A_sh, const float* __restrict__ A_tasks,
    const float* __restrict__ B_sh, const float* __restrict__ B_tasks) {
    const int bx = blockIdx.x;
    const int tid = threadIdx.x;

    if (bx >= 512) {
        if (bx < 1024) {                       // W: 512 blocks * 2048 elems
            size_t i = ((size_t)(bx - 512) * 256 + tid) * 8;
            cvt8(W + i, g_wh + i);
        } else {                               // B: 40 blocks * 2048 elems
            int i = (bx - 1024) * 2048 + tid * 8;
            const float* src = (i < N_TOT * RNK) ? (B_sh + i)
                                                 : (B_tasks + (i - N_TOT * RNK));
            cvt8(src, g_bh + i);
        }
        return;
    }

    extern __shared__ char smc[];
    const int lane = tid & 31, wid = tid >> 5;
    const int warpM = wid >> 1, warpN = wid & 1;   // 4 x 2, warp 16x40
    const int bm = bx;
    const int g = lane >> 2, tg = lane & 3;

    float acc[5][4];
#pragma unroll
    for (int j = 0; j < 5; j++)
#pragma unroll
        for (int q = 0; q < 4; q++) acc[j][q] = 0.f;

    auto ld_stage = [&](int buf, int kt) {
        const float* ax = x + (size_t)(bm * X_BM) * K_TOT + kt * 32;
        char* ad = smc + buf * X_STG;
        char* bd = ad + X_ASTG;
        // x: f32, 128B rows, XOR-8 swizzle, 512 chunks
#pragma unroll
        for (int i = 0; i < 2; i++) {
            int idx = tid + i * 256;
            int r = idx >> 3, c = idx & 7;
            CP16(smem_u32(ad + r * 128 + ((c ^ (r & 7)) << 4)), ax + (size_t)r * K_TOT + c * 4);
        }
        // A_all: f32, 80 rows x 128B, 640 chunks
#pragma unroll
        for (int i = 0; i < 3; i++) {
            int idx = tid + i * 256;
            if (idx < 640) {
                int r = idx >> 3, c = idx & 7;
                const float* src = (r < RNK)
                    ? (A_sh + (size_t)r * K_TOT + kt * 32 + c * 4)
                    : (A_tasks + (size_t)(r - RNK) * K_TOT + kt * 32 + c * 4);
                CP16(smem_u32(bd + r * 128 + ((c ^ (r & 7)) << 4)), src);
            }
        }
    };

    ld_stage(0, 0); CPC();
    ld_stage(1, 1); CPC();

    const int wr_r = tid >> 2, wr_c = tid & 3;   // g_xh writeback mapping

    const int KT = K_TOT / 32;
    for (int kt = 0; kt < KT; kt++) {
        CPW(1);
        __syncthreads();
        if (kt + 2 < KT) ld_stage((kt + 2) % 3, kt + 2);
        CPC();

        const char* A = smc + (kt % 3) * X_STG;
        const char* B = A + X_ASTG;

        // B fragments: f32 -> fp16 in registers (rows n, k-chunk [8tg,8tg+8))
        uint4 bq[5];
#pragma unroll
        for (int nt = 0; nt < 5; nt++) {
            int n = warpN * 40 + nt * 8 + g;
            int c0 = (2 * tg) ^ (n & 7), c1 = (2 * tg + 1) ^ (n & 7);
            float4 f0 = *(const float4*)(B + n * 128 + (c0 << 4));
            float4 f1 = *(const float4*)(B + n * 128 + (c1 << 4));
            __half2 p0 = __floats2half2_rn(f0.x, f0.y), p1 = __floats2half2_rn(f0.z, f0.w);
            __half2 p2 = __floats2half2_rn(f1.x, f1.y), p3 = __floats2half2_rn(f1.z, f1.w);
            bq[nt].x = *(unsigned*)&p0; bq[nt].y = *(unsigned*)&p1;
            bq[nt].z = *(unsigned*)&p2; bq[nt].w = *(unsigned*)&p3;
        }
        // A fragments: rows r0, r0+8
        int r0 = warpM * 16 + g;
        unsigned h0[4], h1[4];
        {
            int c0 = (2 * tg) ^ (r0 & 7), c1 = (2 * tg + 1) ^ (r0 & 7);
            float4 f0 = *(const float4*)(A + r0 * 128 + (c0 << 4));
            float4 f1 = *(const float4*)(A + r0 * 128 + (c1 << 4));
            __half2 t0 = __floats2half2_rn(f0.x, f0.y), t1 = __floats2half2_rn(f0.z, f0.w);
            __half2 t2 = __floats2half2_rn(f1.x, f1.y), t3 = __floats2half2_rn(f1.z, f1.w);
            h0[0] = *(unsigned*)&t0; h0[1] = *(unsigned*)&t1;
            h0[2] = *(unsigned*)&t2; h0[3] = *(unsigned*)&t3;
            int r1 = r0 + 8;
            int d0 = (2 * tg) ^ (r1 & 7), d1 = (2 * tg + 1) ^ (r1 & 7);
            float4 q0 = *(const float4*)(A + r1 * 128 + (d0 << 4));
            float4 q1 = *(const float4*)(A + r1 * 128 + (d1 << 4));
            __half2 u0 = __floats2half2_rn(q0.x, q0.y), u1 = __floats2half2_rn(q0.z, q0.w);
            __half2 u2 = __floats2half2_rn(q1.x, q1.y), u3 = __floats2half2_rn(q1.z, q1.w);
            h1[0] = *(unsigned*)&u0; h1[1] = *(unsigned*)&u1;
            h1[2] = *(unsigned*)&u2; h1[3] = *(unsigned*)&u3;
        }
#pragma unroll
        for (int nt = 0; nt < 5; nt++) {
            mma16(acc[nt], h0[0], h1[0], h0[1], h1[1], bq[nt].x, bq[nt].y);
            mma16(acc[nt], h0[2], h1[2], h0[3], h1[3], bq[nt].z, bq[nt].w);
        }

        // writeback: convert this x stage to fp16 -> g_xh
        {
            int c0 = (2 * wr_c) ^ (wr_r & 7), c1 = (2 * wr_c + 1) ^ (wr_r & 7);
            float4 f0 = *(const float4*)(A + wr_r * 128 + (c0 << 4));
            float4 f1 = *(const float4*)(A + wr_r * 128 + (c1 << 4));
            __half2 t0 = __floats2half2_rn(f0.x, f0.y), t1 = __floats2half2_rn(f0.z, f0.w);
            __half2 t2 = __floats2half2_rn(f1.x, f1.y), t3 = __floats2half2_rn(f1.z, f1.w);
            uint4 o;
            o.x = *(unsigned*)&t0; o.y = *(unsigned*)&t1;
            o.z = *(unsigned*)&t2; o.w = *(unsigned*)&t3;
            *(uint4*)(g_xh + (size_t)(bm * X_BM + wr_r) * K_TOT + kt * 32 + wr_c * 8) = o;
        }
    }

#pragma unroll
    for (int nt = 0; nt < 5; nt++) {
        int row = bm * X_BM + warpM * 16 + g;
        int col = warpN * 40 + nt * 8 + tg * 2;
        *(__half2*)&g_xah[(size_t)row * XA_COLS + col] =
            __floats2half2_rn(acc[nt][0], acc[nt][1]);
        *(__half2*)&g_xah[(size_t)(row + 8) * XA_COLS + col] =
            __floats2half2_rn(acc[nt][2], acc[nt][3]);
    }
}

// ---------------------------------------------------------------------------
// Kernel 2: main fused GEMM, fp16 m16n8k16. CTA 128x128, 256 threads,
// 8 warps as 2x4 (warp 64x32), occupancy 2. 4-stage pipeline, 64B swizzle.
// ---------------------------------------------------------------------------
#define BM 128
#define BN 128
#define STG_B 16384                 // (128+128) rows * 64 B
#define OFF_XA (4 * STG_B)          // 65536 ; XA tile 128*160B
#define OFF_BEP (OFF_XA + BM * 160)         // 86016 ; Bep 5*128*32
#define SMEM_MAIN (OFF_BEP + NPLANE * 128 * 32)  // 106496
#define NTHR 256

__global__ void __launch_bounds__(NTHR, 2) main_kernel(
    const float* __restrict__ bias, const float* __restrict__ scales,
    float* __restrict__ out) {
    extern __shared__ char smc[];
    const int tid = threadIdx.x;
    const int lane = tid & 31, wid = tid >> 5;
    const int warpM = wid >> 2, warpN = wid & 3;   // 2 x 4 of 64x32
    const int bn = blockIdx.x, bm = blockIdx.y;
    const int g = lane >> 2, tg = lane & 3;

    float acc[4][4][4];
#pragma unroll
    for (int i = 0; i < 4; i++)
#pragma unroll
        for (int j = 0; j < 4; j++)
#pragma unroll
            for (int q = 0; q < 4; q++) acc[i][j][q] = 0.f;

    auto ld_stage = [&](int buf, int kt) {
        const __half* ax = g_xh + (size_t)(bm * BM) * K_TOT + kt * 32;
        const __half* bw = g_wh + (size_t)(bn * BN) * K_TOT + kt * 32;
        char* ad = smc + buf * STG_B;
        char* bd = ad + BM * 64;
#pragma unroll
        for (int i = 0; i < 2; i++) {
            int idx = tid + i * NTHR;
            int r = idx >> 2, c = idx & 3;
            CP16(smem_u32(ad + r * 64 + ((c ^ (r & 3)) << 4)), ax + (size_t)r * K_TOT + c * 8);
        }
#pragma unroll
        for (int i = 0; i < 2; i++) {
            int idx = tid + i * NTHR;
            int r = idx >> 2, c = idx & 3;
            CP16(smem_u32(bd + r * 64 + ((c ^ (r & 3)) << 4)), bw + (size_t)r * K_TOT + c * 8);
        }
    };

    // Prologue: stages first, epilogue tiles folded into group 2.
    ld_stage(0, 0); CPC();
    ld_stage(1, 1); CPC();
    ld_stage(2, 2);
    {
        const __half* xs = g_xah + (size_t)(bm * BM) * XA_COLS;
#pragma unroll
        for (int i = 0; i < 5; i++) {           // 1280 chunks XA
            int idx = tid + i * NTHR;
            int r = idx / 10, c = idx % 10;
            CP16(smem_u32(smc + OFF_XA + r * 160 + c * 16), xs + (size_t)r * XA_COLS + c * 8);
        }
#pragma unroll
        for (int i = 0; i < 5; i++) {           // 1280 chunks Bep
            int idx = tid + i * NTHR;
            int p = idx >> 8, n = (idx >> 1) & 127, c = idx & 1;
            CP16(smem_u32(smc + OFF_BEP + (p * 128 + n) * 32 + c * 16),
                 g_bh + ((size_t)p * N_TOT + bn * BN + n) * RNK + c * 8);
        }
    }
    CPC();

    const int KT = K_TOT / 32;  // 32
    for (int kt = 0; kt < KT; kt++) {
        CPW(2);
        __syncthreads();
        if (kt + 3 < KT) ld_stage((kt + 3) & 3, kt + 3);
        CPC();

        const char* A = smc + (kt & 3) * STG_B;
        const char* B = A + BM * 64;

        uint4 bq[4];
#pragma unroll
        for (int nt = 0; nt < 4; nt++) {
            int n = warpN * 32 + nt * 8 + g;
            bq[nt] = *(const uint4*)(B + n * 64 + ((tg ^ (n & 3)) << 4));
        }
#pragma unroll
        for (int mt = 0; mt < 4; mt++) {
            int r0 = warpM * 64 + mt * 16 + g;
            int sw = (tg ^ (r0 & 3)) << 4;
            uint4 a0 = *(const uint4*)(A + r0 * 64 + sw);
            uint4 a1 = *(const uint4*)(A + (r0 + 8) * 64 + sw);
#pragma unroll
            for (int nt = 0; nt < 4; nt++)
                mma16(acc[mt][nt], a0.x, a1.x, a0.y, a1.y, bq[nt].x, bq[nt].y);
#pragma unroll
            for (int nt = 0; nt < 4; nt++)
                mma16(acc[mt][nt], a0.z, a1.z, a0.w, a1.w, bq[nt].z, bq[nt].w);
        }
    }

    // hoist bias/scales before the pipeline drain
    float scl[NPLANE];
    scl[0] = 1.f;
#pragma unroll
    for (int p = 1; p < NPLANE; p++) scl[p] = __ldg(&scales[p - 1]);
    float bv0[4], bv1[4];
#pragma unroll
    for (int nt = 0; nt < 4; nt++) {
        int c = bn * BN + warpN * 32 + nt * 8 + tg * 2;
        bv0[nt] = __ldg(&bias[c]);
        bv1[nt] = __ldg(&bias[c + 1]);
    }

    CPW(0);
    __syncthreads();

#pragma unroll
    for (int nt = 0; nt < 4; nt++)
#pragma unroll
        for (int mt = 0; mt < 4; mt++) {
            acc[mt][nt][0] += bv0[nt]; acc[mt][nt][1] += bv1[nt];
            acc[mt][nt][2] += bv0[nt]; acc[mt][nt][3] += bv1[nt];
        }

    const char* XAs = smc + OFF_XA;
    const char* Bep = smc + OFF_BEP;
    const int sH = tg >> 1, sL = tg & 1;   // permuted k16 mapping

#pragma unroll
    for (int p = 0; p < NPLANE; p++) {
        float s = scl[p];
        float* op = out + (size_t)p * M_TOT * N_TOT;

        unsigned bb[4][2];
#pragma unroll
        for (int nt = 0; nt < 4; nt++) {
            int n = warpN * 32 + nt * 8 + g;
            uint4 v = *(const uint4*)(Bep + (p * 128 + n) * 32 + sL * 16);
            bb[nt][0] = sH ? v.z : v.x;
            bb[nt][1] = sH ? v.w : v.y;
        }

#pragma unroll
        for (int mt = 0; mt < 4; mt++) {
            int r0 = warpM * 64 + mt * 16 + g;
            uint4 x0 = *(const uint4*)(XAs + r0 * 160 + p * 32 + sL * 16);
            uint4 x1 = *(const uint4*)(XAs + (r0 + 8) * 160 + p * 32 + sL * 16);
            unsigned a0 = sH ? x0.z : x0.x, a2 = sH ? x0.w : x0.y;
            unsigned a1 = sH ? x1.z : x1.x, a3 = sH ? x1.w : x1.y;

            float d[4][4];
#pragma unroll
            for (int nt = 0; nt < 4; nt++) {
#pragma unroll
                for (int q = 0; q < 4; q++) d[nt][q] = 0.f;
                mma16(d[nt], a0, a1, a2, a3, bb[nt][0], bb[nt][1]);
            }

            int row = bm * BM + r0;
#pragma unroll
            for (int nt = 0; nt < 4; nt++) {
                int col = bn * BN + warpN * 32 + nt * 8 + tg * 2;
                float2 v0 = make_float2(acc[mt][nt][0] + s * d[nt][0],
                                        acc[mt][nt][1] + s * d[nt][1]);
                float2 v1 = make_float2(acc[mt][nt][2] + s * d[nt][2],
                                        acc[mt][nt][3] + s * d[nt][3]);
                __stcs((float2*)&op[(size_t)row * N_TOT + col], v0);
                __stcs((float2*)&op[(size_t)(row + 8) * N_TOT + col], v1);
            }
        }
    }
}

// ---------------------------------------------------------------------------
extern "C" void kernel_launch(void* const* d_in, const int* in_sizes, int n_in,
                              void* d_out, int out_size) {
    const float* x = (const float*)d_in[0];
    const float* W = (const float*)d_in[1];
    const float* b = (const float*)d_in[2];
    const float* A_sh = (const float*)d_in[3];
    const float* B_sh = (const float*)d_in[4];
    const float* A_tasks = (const float*)d_in[5];
    const float* B_tasks = (const float*)d_in[6];
    const float* scales = (const float*)d_in[7];
    float* out = (float*)d_out;

    cudaFuncSetAttribute(xa_kernel, cudaFuncAttributeMaxDynamicSharedMemorySize, X_SMEM);
    cudaFuncSetAttribute(main_kernel, cudaFuncAttributeMaxDynamicSharedMemorySize, SMEM_MAIN);

    xa_kernel<<<1064, 256, X_SMEM>>>(x, W, A_sh, A_tasks, B_sh, B_tasks);
    main_kernel<<<dim3(N_TOT / BN, M_TOT / BM), NTHR, SMEM_MAIN>>>(b, scales, out);
    (void)in_sizes; (void)n_in; (void)out_size;
}